// round 4
// baseline (speedup 1.0000x reference)
#include <cuda_runtime.h>

// Problem constants (fixed shapes)
#define B_  32
#define T_  4096
#define H_  256
#define IN_ 128
#define P_  64

// Scratch: pre-activations and hidden states, [T][B][H] layout (t-major).
__device__ float g_pre[(size_t)T_ * B_ * H_];
__device__ float g_h  [(size_t)T_ * B_ * H_];

// ---------------- packed f32x2 helpers (FFMA2: 2 FMAs per issue) ----------------
__device__ __forceinline__ void ffma2(unsigned long long& d, unsigned long long a,
                                      unsigned long long b) {
    asm("fma.rn.f32x2 %0, %1, %2, %0;" : "+l"(d) : "l"(a), "l"(b));
}
__device__ __forceinline__ unsigned long long dup2(float a) {
    unsigned long long r;
    asm("mov.b64 %0, {%1, %1};" : "=l"(r) : "f"(a));
    return r;
}
__device__ __forceinline__ float2 unpack2(unsigned long long v) {
    float2 r;
    asm("mov.b64 {%0, %1}, %2;" : "=f"(r.x), "=f"(r.y) : "l"(v));
    return r;
}

// ---------------------------------------------------------------------------
// Tiled fp32 GEMM:  C[m][n] = act( sum_k A[m][k] * W[n][k] + bias1[n] (+ bias2[n]) )
// Tile: 64(M) x 64(N) x 32(K), 256 threads, 4x4 micro-tile per thread.
// ---------------------------------------------------------------------------
template <bool PERM_IN, bool PERM_OUT, bool SIG>
__global__ void __launch_bounds__(256) gemm_k(
    const float* __restrict__ A, const float* __restrict__ W,
    const float* __restrict__ b1, const float* __restrict__ b2,
    float* __restrict__ C, int K, int N)
{
    __shared__ float AsT[32][68];  // [k][m]
    __shared__ float BsT[32][68];  // [k][n]

    const int tid = threadIdx.x;
    const int tx = tid & 15;
    const int ty = tid >> 4;
    const int m0 = blockIdx.x * 64;
    const int n0 = blockIdx.y * 64;

    unsigned long long acc[4][2];
#pragma unroll
    for (int i = 0; i < 4; ++i) { acc[i][0] = 0ull; acc[i][1] = 0ull; }

    const int r0 = tid >> 3;
    const int q0 = tid & 7;
    const int r1 = r0 + 32;

    long ar0, ar1;
    if (PERM_IN) {
        int ma = m0 + r0, mb = m0 + r1;
        ar0 = (long)(ma & 31) * T_ + (ma >> 5);
        ar1 = (long)(mb & 31) * T_ + (mb >> 5);
    } else {
        ar0 = m0 + r0;
        ar1 = m0 + r1;
    }
    const float* Ap0 = A + ar0 * (long)K + q0 * 4;
    const float* Ap1 = A + ar1 * (long)K + q0 * 4;
    const float* Wp0 = W + (long)(n0 + r0) * K + q0 * 4;
    const float* Wp1 = W + (long)(n0 + r1) * K + q0 * 4;

    for (int kt = 0; kt < K; kt += 32) {
        float4 a0 = *(const float4*)(Ap0 + kt);
        float4 a1 = *(const float4*)(Ap1 + kt);
        float4 w0 = *(const float4*)(Wp0 + kt);
        float4 w1 = *(const float4*)(Wp1 + kt);
        __syncthreads();
        AsT[q0 * 4 + 0][r0] = a0.x; AsT[q0 * 4 + 1][r0] = a0.y;
        AsT[q0 * 4 + 2][r0] = a0.z; AsT[q0 * 4 + 3][r0] = a0.w;
        AsT[q0 * 4 + 0][r1] = a1.x; AsT[q0 * 4 + 1][r1] = a1.y;
        AsT[q0 * 4 + 2][r1] = a1.z; AsT[q0 * 4 + 3][r1] = a1.w;
        BsT[q0 * 4 + 0][r0] = w0.x; BsT[q0 * 4 + 1][r0] = w0.y;
        BsT[q0 * 4 + 2][r0] = w0.z; BsT[q0 * 4 + 3][r0] = w0.w;
        BsT[q0 * 4 + 0][r1] = w1.x; BsT[q0 * 4 + 1][r1] = w1.y;
        BsT[q0 * 4 + 2][r1] = w1.z; BsT[q0 * 4 + 3][r1] = w1.w;
        __syncthreads();

#pragma unroll
        for (int kk = 0; kk < 32; ++kk) {
            float4 a4 = *(const float4*)&AsT[kk][ty * 4];
            ulonglong2 bb = *(const ulonglong2*)&BsT[kk][tx * 4];
            unsigned long long d;
            d = dup2(a4.x); ffma2(acc[0][0], d, bb.x); ffma2(acc[0][1], d, bb.y);
            d = dup2(a4.y); ffma2(acc[1][0], d, bb.x); ffma2(acc[1][1], d, bb.y);
            d = dup2(a4.z); ffma2(acc[2][0], d, bb.x); ffma2(acc[2][1], d, bb.y);
            d = dup2(a4.w); ffma2(acc[3][0], d, bb.x); ffma2(acc[3][1], d, bb.y);
        }
    }

    float4 bv = *(const float4*)&b1[n0 + tx * 4];
    if (b2) {
        float4 b2v = *(const float4*)&b2[n0 + tx * 4];
        bv.x += b2v.x; bv.y += b2v.y; bv.z += b2v.z; bv.w += b2v.w;
    }

#pragma unroll
    for (int i = 0; i < 4; ++i) {
        int m = m0 + ty * 4 + i;
        float2 c01 = unpack2(acc[i][0]);
        float2 c23 = unpack2(acc[i][1]);
        float4 v;
        v.x = c01.x + bv.x; v.y = c01.y + bv.y;
        v.z = c23.x + bv.z; v.w = c23.y + bv.w;
        if (SIG) {
            v.x = 1.f / (1.f + expf(-v.x));
            v.y = 1.f / (1.f + expf(-v.y));
            v.z = 1.f / (1.f + expf(-v.z));
            v.w = 1.f / (1.f + expf(-v.w));
        }
        long orow = PERM_OUT ? ((long)(m & 31) * T_ + (m >> 5)) : (long)m;
        *(float4*)(C + orow * (long)N + n0 + tx * 4) = v;
    }
}

// ---------------------------------------------------------------------------
// Recurrent scan, W_hh fully register-resident, 4-way output split.
// One CTA per batch element, 1024 threads. Thread (j, c=0..3) computes a
// quarter of output j's dot product: it owns the 16 16B-chunks of W_hh[j]
// with chunk index congruent to c (mod 4) -> 16 ulonglong2 = 32 regs.
// Per step: 16 broadcast LDS.128 (4 distinct 16B addrs per warp -> 64B/inst,
// crossbar-cheap) + 32 FFMA2, then 2x shfl.bfly reduction across the group.
// h double-buffered in 2KB smem; pre[t+1] prefetched one step ahead.
//   h_new[j] = tanh( pre[t][b][j] + sum_k h[k] * W_hh[j][k] )
// ---------------------------------------------------------------------------
__global__ void __launch_bounds__(1024, 1) rnn_scan_k(
    const float* __restrict__ Whh, const float* __restrict__ pre,
    float* __restrict__ hout)
{
    __shared__ float hbuf[2][H_];

    const int b = blockIdx.x;
    const int tid = threadIdx.x;
    const int j = tid >> 2;   // output index 0..255
    const int c = tid & 3;    // k-chunk phase 0..3

    // Register-resident W slice: chunks 4i+c, i = 0..15 (chunk = 4 floats)
    ulonglong2 wr[16];
    {
        const float* wrow = Whh + (long)j * H_ + c * 4;
#pragma unroll
        for (int i = 0; i < 16; ++i)
            wr[i] = *(const ulonglong2*)(wrow + i * 16);
    }

    if (tid < H_) hbuf[0][tid] = 0.f;  // h0 = zeros
    __syncthreads();

    const float* preb = pre + b * H_ + j;
    float* outb = hout + b * H_ + j;

    float pre_cur = (c == 0) ? preb[0] : 0.f;
    int cur = 0;

    for (int t = 0; t < T_; ++t) {
        // prefetch next pre-activation under the dot product
        float pre_next = 0.f;
        if (c == 0 && t + 1 < T_) pre_next = preb[(size_t)(t + 1) * (B_ * H_)];

        const float* h = hbuf[cur] + c * 4;
        unsigned long long a0 = 0ull, a1 = 0ull, a2 = 0ull, a3 = 0ull;
#pragma unroll
        for (int i = 0; i < 16; i += 2) {
            ulonglong2 h2a = *(const ulonglong2*)(h + i * 16);
            ulonglong2 h2b = *(const ulonglong2*)(h + (i + 1) * 16);
            ffma2(a0, h2a.x, wr[i].x);
            ffma2(a1, h2a.y, wr[i].y);
            ffma2(a2, h2b.x, wr[i + 1].x);
            ffma2(a3, h2b.y, wr[i + 1].y);
        }
        float2 s0 = unpack2(a0), s1 = unpack2(a1);
        float2 s2 = unpack2(a2), s3 = unpack2(a3);
        float dot = ((s0.x + s0.y) + (s1.x + s1.y)) +
                    ((s2.x + s2.y) + (s3.x + s3.y));
        dot += __shfl_xor_sync(0xffffffffu, dot, 1);
        dot += __shfl_xor_sync(0xffffffffu, dot, 2);

        if (c == 0) {
            float v = tanhf(pre_cur + dot);
            hbuf[cur ^ 1][j] = v;
            outb[(size_t)t * (B_ * H_)] = v;
        }
        __syncthreads();

        cur ^= 1;
        pre_cur = pre_next;
    }
}

// ---------------------------------------------------------------------------
extern "C" void kernel_launch(void* const* d_in, const int* in_sizes, int n_in,
                              void* d_out, int out_size)
{
    const float* input = (const float*)d_in[0];
    const float* W_ih0 = (const float*)d_in[1];
    const float* W_hh0 = (const float*)d_in[2];
    const float* b_ih0 = (const float*)d_in[3];
    const float* b_hh0 = (const float*)d_in[4];
    const float* W_ih1 = (const float*)d_in[5];
    const float* W_hh1 = (const float*)d_in[6];
    const float* b_ih1 = (const float*)d_in[7];
    const float* b_hh1 = (const float*)d_in[8];
    const float* fc_W  = (const float*)d_in[9];
    const float* fc_b  = (const float*)d_in[10];
    float* out = (float*)d_out;

    float *pre, *hh;
    cudaGetSymbolAddress((void**)&pre, g_pre);
    cudaGetSymbolAddress((void**)&hh, g_h);

    dim3 blk(256);
    dim3 gA((B_ * T_) / 64, H_ / 64);   // 2048 x 4
    dim3 gF((B_ * T_) / 64, P_ / 64);   // 2048 x 1

    // Layer 0: pre0 = x @ W_ih0^T + b_ih0 + b_hh0   -> g_pre [T][B][H]
    gemm_k<true, false, false><<<gA, blk>>>(input, W_ih0, b_ih0, b_hh0, pre, IN_, H_);
    // Layer 0 recurrence -> g_h = h1 [T][B][H]
    rnn_scan_k<<<B_, 1024>>>(W_hh0, pre, hh);
    // Layer 1: pre1 = h1 @ W_ih1^T + b_ih1 + b_hh1  -> g_pre
    gemm_k<false, false, false><<<gA, blk>>>(hh, W_ih1, b_ih1, b_hh1, pre, H_, H_);
    // Layer 1 recurrence -> g_h = h2
    rnn_scan_k<<<B_, 1024>>>(W_hh1, pre, hh);
    // FC head: out[b*T+t][p] = sigmoid(h2 @ fc_W^T + fc_b)
    gemm_k<false, true, true><<<gF, blk>>>(hh, fc_W, fc_b, nullptr, out, H_, P_);
}

// round 7
// speedup vs baseline: 1.8842x; 1.8842x over previous
#include <cuda_runtime.h>
#include <cstdint>
#include <cstddef>

// Problem constants (fixed shapes)
#define B_  32
#define T_  4096
#define H_  256
#define IN_ 128
#define P_  64

// Scratch: pre-activations and hidden states, [T][B][H] layout (t-major).
__device__ float g_pre[(size_t)T_ * B_ * H_];
__device__ float g_h  [(size_t)T_ * B_ * H_];

// ---------------- packed f32x2 helpers (FFMA2: 2 FMAs per issue) ----------------
__device__ __forceinline__ void ffma2(unsigned long long& d, unsigned long long a,
                                      unsigned long long b) {
    asm("fma.rn.f32x2 %0, %1, %2, %0;" : "+l"(d) : "l"(a), "l"(b));
}
__device__ __forceinline__ unsigned long long dup2(float a) {
    unsigned long long r;
    asm("mov.b64 %0, {%1, %1};" : "=l"(r) : "f"(a));
    return r;
}
__device__ __forceinline__ float2 unpack2(unsigned long long v) {
    float2 r;
    asm("mov.b64 {%0, %1}, %2;" : "=f"(r.x), "=f"(r.y) : "l"(v));
    return r;
}

// ---------------------------------------------------------------------------
// Tiled fp32 GEMM:  C[m][n] = act( sum_k A[m][k] * W[n][k] + bias1[n] (+ bias2[n]) )
// Tile: 64(M) x 64(N) x 32(K), 256 threads, 4x4 micro-tile per thread.
// ---------------------------------------------------------------------------
template <bool PERM_IN, bool PERM_OUT, bool SIG>
__global__ void __launch_bounds__(256) gemm_k(
    const float* __restrict__ A, const float* __restrict__ W,
    const float* __restrict__ b1, const float* __restrict__ b2,
    float* __restrict__ C, int K, int N)
{
    __shared__ float AsT[32][68];  // [k][m]
    __shared__ float BsT[32][68];  // [k][n]

    const int tid = threadIdx.x;
    const int tx = tid & 15;
    const int ty = tid >> 4;
    const int m0 = blockIdx.x * 64;
    const int n0 = blockIdx.y * 64;

    unsigned long long acc[4][2];
#pragma unroll
    for (int i = 0; i < 4; ++i) { acc[i][0] = 0ull; acc[i][1] = 0ull; }

    const int r0 = tid >> 3;
    const int q0 = tid & 7;
    const int r1 = r0 + 32;

    long ar0, ar1;
    if (PERM_IN) {
        int ma = m0 + r0, mb = m0 + r1;
        ar0 = (long)(ma & 31) * T_ + (ma >> 5);
        ar1 = (long)(mb & 31) * T_ + (mb >> 5);
    } else {
        ar0 = m0 + r0;
        ar1 = m0 + r1;
    }
    const float* Ap0 = A + ar0 * (long)K + q0 * 4;
    const float* Ap1 = A + ar1 * (long)K + q0 * 4;
    const float* Wp0 = W + (long)(n0 + r0) * K + q0 * 4;
    const float* Wp1 = W + (long)(n0 + r1) * K + q0 * 4;

    for (int kt = 0; kt < K; kt += 32) {
        float4 a0 = *(const float4*)(Ap0 + kt);
        float4 a1 = *(const float4*)(Ap1 + kt);
        float4 w0 = *(const float4*)(Wp0 + kt);
        float4 w1 = *(const float4*)(Wp1 + kt);
        __syncthreads();
        AsT[q0 * 4 + 0][r0] = a0.x; AsT[q0 * 4 + 1][r0] = a0.y;
        AsT[q0 * 4 + 2][r0] = a0.z; AsT[q0 * 4 + 3][r0] = a0.w;
        AsT[q0 * 4 + 0][r1] = a1.x; AsT[q0 * 4 + 1][r1] = a1.y;
        AsT[q0 * 4 + 2][r1] = a1.z; AsT[q0 * 4 + 3][r1] = a1.w;
        BsT[q0 * 4 + 0][r0] = w0.x; BsT[q0 * 4 + 1][r0] = w0.y;
        BsT[q0 * 4 + 2][r0] = w0.z; BsT[q0 * 4 + 3][r0] = w0.w;
        BsT[q0 * 4 + 0][r1] = w1.x; BsT[q0 * 4 + 1][r1] = w1.y;
        BsT[q0 * 4 + 2][r1] = w1.z; BsT[q0 * 4 + 3][r1] = w1.w;
        __syncthreads();

#pragma unroll
        for (int kk = 0; kk < 32; ++kk) {
            float4 a4 = *(const float4*)&AsT[kk][ty * 4];
            ulonglong2 bb = *(const ulonglong2*)&BsT[kk][tx * 4];
            unsigned long long d;
            d = dup2(a4.x); ffma2(acc[0][0], d, bb.x); ffma2(acc[0][1], d, bb.y);
            d = dup2(a4.y); ffma2(acc[1][0], d, bb.x); ffma2(acc[1][1], d, bb.y);
            d = dup2(a4.z); ffma2(acc[2][0], d, bb.x); ffma2(acc[2][1], d, bb.y);
            d = dup2(a4.w); ffma2(acc[3][0], d, bb.x); ffma2(acc[3][1], d, bb.y);
        }
    }

    float4 bv = *(const float4*)&b1[n0 + tx * 4];
    if (b2) {
        float4 b2v = *(const float4*)&b2[n0 + tx * 4];
        bv.x += b2v.x; bv.y += b2v.y; bv.z += b2v.z; bv.w += b2v.w;
    }

#pragma unroll
    for (int i = 0; i < 4; ++i) {
        int m = m0 + ty * 4 + i;
        float2 c01 = unpack2(acc[i][0]);
        float2 c23 = unpack2(acc[i][1]);
        float4 v;
        v.x = c01.x + bv.x; v.y = c01.y + bv.y;
        v.z = c23.x + bv.z; v.w = c23.y + bv.w;
        if (SIG) {
            v.x = 1.f / (1.f + expf(-v.x));
            v.y = 1.f / (1.f + expf(-v.y));
            v.z = 1.f / (1.f + expf(-v.z));
            v.w = 1.f / (1.f + expf(-v.w));
        }
        long orow = PERM_OUT ? ((long)(m & 31) * T_ + (m >> 5)) : (long)m;
        *(float4*)(C + orow * (long)N + n0 + tx * 4) = v;
    }
}

// ---------------------------------------------------------------------------
// Recurrent scan on a 2-CTA cluster per batch element.
// Cluster rank r owns outputs j in [r*128, r*128+128). 512 threads/CTA:
// thread (j_local, c=0..3) owns the 16 16B-chunks of W_hh[j] with chunk
// index == c (mod 4) -> 16 ulonglong2 = 32 regs, loaded once.
// Per step: 16 broadcast LDS.128 + 32 FFMA2 per thread, 2x shfl reduce;
// c==0 threads write h to the LOCAL buffer and the PEER CTA's buffer
// (st.shared::cluster), then barrier.cluster (release/acquire) syncs the
// step. h double-buffered -> single sync per step, no WAR hazard.
//   h_new[j] = tanh( pre[t][b][j] + sum_k h[k] * W_hh[j][k] )
// ---------------------------------------------------------------------------
__global__ void __launch_bounds__(512, 1) __cluster_dims__(2, 1, 1)
rnn_scan_k(const float* __restrict__ Whh, const float* __restrict__ pre,
           float* __restrict__ hout)
{
    __shared__ float hbuf[2][H_];

    const int b = blockIdx.x >> 1;
    unsigned int rank;
    asm("mov.u32 %0, %%cluster_ctarank;" : "=r"(rank));
    const unsigned int peer = rank ^ 1u;

    const int tid = threadIdx.x;
    const int jl  = tid >> 2;          // local output 0..127
    const int c   = tid & 3;           // k-chunk phase
    const int j   = (int)rank * 128 + jl;  // global output 0..255

    // Register-resident W slice: chunks 4i+c, i = 0..15
    ulonglong2 wr[16];
    {
        const float* wrow = Whh + (long)j * H_ + c * 4;
#pragma unroll
        for (int i = 0; i < 16; ++i)
            wr[i] = *(const ulonglong2*)(wrow + i * 16);
    }

    if (tid < H_) hbuf[0][tid] = 0.f;  // h0 = zeros (local copy)
    __syncthreads();
    // Make sure both CTAs are initialized before the stepped protocol starts.
    asm volatile("barrier.cluster.arrive.aligned;" ::: "memory");
    asm volatile("barrier.cluster.wait.aligned;" ::: "memory");

    // Peer smem address for my output slot (double buffer handled by offset)
    unsigned int loc0 = (unsigned int)__cvta_generic_to_shared(&hbuf[0][j]);
    unsigned int rem0;
    asm("mapa.shared::cluster.u32 %0, %1, %2;" : "=r"(rem0) : "r"(loc0), "r"(peer));

    const float* preb = pre + b * H_ + j;
    float* outb = hout + b * H_ + j;

    float pre_cur = (c == 0) ? preb[0] : 0.f;
    int cur = 0;

    for (int t = 0; t < T_; ++t) {
        // prefetch next pre-activation under the dot product
        float pre_next = 0.f;
        if (c == 0 && t + 1 < T_) pre_next = preb[(size_t)(t + 1) * (B_ * H_)];

        const float* h = hbuf[cur] + c * 4;
        unsigned long long a0 = 0ull, a1 = 0ull, a2 = 0ull, a3 = 0ull;
#pragma unroll
        for (int i = 0; i < 16; i += 2) {
            ulonglong2 h2a = *(const ulonglong2*)(h + i * 16);
            ulonglong2 h2b = *(const ulonglong2*)(h + (i + 1) * 16);
            ffma2(a0, h2a.x, wr[i].x);
            ffma2(a1, h2a.y, wr[i].y);
            ffma2(a2, h2b.x, wr[i + 1].x);
            ffma2(a3, h2b.y, wr[i + 1].y);
        }
        float2 s0 = unpack2(a0), s1 = unpack2(a1);
        float2 s2 = unpack2(a2), s3 = unpack2(a3);
        float dot = ((s0.x + s0.y) + (s1.x + s1.y)) +
                    ((s2.x + s2.y) + (s3.x + s3.y));
        dot += __shfl_xor_sync(0xffffffffu, dot, 1);
        dot += __shfl_xor_sync(0xffffffffu, dot, 2);

        if (c == 0) {
            float v = tanhf(pre_cur + dot);
            int nxt = cur ^ 1;
            hbuf[nxt][j] = v;  // local copy
            // peer copy (fire-and-forget DSMEM store; ordered by the
            // release semantics of barrier.cluster.arrive below)
            asm volatile("st.shared::cluster.f32 [%0], %1;"
                         :: "r"(rem0 + (unsigned int)(nxt * H_ * 4)), "f"(v));
            outb[(size_t)t * (B_ * H_)] = v;
        }
        // step sync: orders DSMEM stores (arrive=release, wait=acquire)
        asm volatile("barrier.cluster.arrive.aligned;" ::: "memory");
        asm volatile("barrier.cluster.wait.aligned;" ::: "memory");

        cur ^= 1;
        pre_cur = pre_next;
    }
}

// ---------------------------------------------------------------------------
extern "C" void kernel_launch(void* const* d_in, const int* in_sizes, int n_in,
                              void* d_out, int out_size)
{
    const float* input = (const float*)d_in[0];
    const float* W_ih0 = (const float*)d_in[1];
    const float* W_hh0 = (const float*)d_in[2];
    const float* b_ih0 = (const float*)d_in[3];
    const float* b_hh0 = (const float*)d_in[4];
    const float* W_ih1 = (const float*)d_in[5];
    const float* W_hh1 = (const float*)d_in[6];
    const float* b_ih1 = (const float*)d_in[7];
    const float* b_hh1 = (const float*)d_in[8];
    const float* fc_W  = (const float*)d_in[9];
    const float* fc_b  = (const float*)d_in[10];
    float* out = (float*)d_out;

    float *pre, *hh;
    cudaGetSymbolAddress((void**)&pre, g_pre);
    cudaGetSymbolAddress((void**)&hh, g_h);

    dim3 blk(256);
    dim3 gA((B_ * T_) / 64, H_ / 64);   // 2048 x 4
    dim3 gF((B_ * T_) / 64, P_ / 64);   // 2048 x 1

    // Layer 0: pre0 = x @ W_ih0^T + b_ih0 + b_hh0   -> g_pre [T][B][H]
    gemm_k<true, false, false><<<gA, blk>>>(input, W_ih0, b_ih0, b_hh0, pre, IN_, H_);
    // Layer 0 recurrence -> g_h = h1 [T][B][H]  (2 CTAs per batch element)
    rnn_scan_k<<<2 * B_, 512>>>(W_hh0, pre, hh);
    // Layer 1: pre1 = h1 @ W_ih1^T + b_ih1 + b_hh1  -> g_pre
    gemm_k<false, false, false><<<gA, blk>>>(hh, W_ih1, b_ih1, b_hh1, pre, H_, H_);
    // Layer 1 recurrence -> g_h = h2
    rnn_scan_k<<<2 * B_, 512>>>(W_hh1, pre, hh);
    // FC head: out[b*T+t][p] = sigmoid(h2 @ fc_W^T + fc_b)
    gemm_k<false, true, true><<<gF, blk>>>(hh, fc_W, fc_b, nullptr, out, H_, P_);
}